// round 10
// baseline (speedup 1.0000x reference)
#include <cuda_runtime.h>
#include <math.h>

#define TT     256   // B*S tiles
#define NTOK   256   // N tokens per tile
#define DMODEL 512
#define NH     8
#define HD     64

typedef unsigned long long u64t;

// ---------------- f32x2 packed-math helpers (B300 FFMA2 path) ---------------
__device__ __forceinline__ u64t pack2(float lo, float hi) {
    u64t r; asm("mov.b64 %0, {%1,%2};" : "=l"(r) : "f"(lo), "f"(hi)); return r;
}
__device__ __forceinline__ void fma2(u64t& d, u64t a, u64t b) {
    asm("fma.rn.f32x2 %0, %1, %2, %0;" : "+l"(d) : "l"(a), "l"(b));
}
__device__ __forceinline__ float2 unpack2(u64t v) {
    float2 f; asm("mov.b64 {%0,%1}, %2;" : "=f"(f.x), "=f"(f.y) : "l"(v)); return f;
}

// ---------------- scratch (device globals: no allocation allowed) -----------
__device__ float g_Q[TT * DMODEL];          // q per tile (with bias)
__device__ float g_P[TT * NH * DMODEL];     // [t][h][d], pre-scaled by 1/8
__device__ float g_Y[TT * NH * DMODEL];     // [t][h][d], softmax-weighted x sums
__device__ float g_ctx[TT * DMODEL];        // concat heads per tile

// ---------------- generic 16x64-tile GEMM: C = A @ B + bias -----------------
// Double-buffered k=64 chunks, register prefetch, f32x2 accumulation.
__global__ __launch_bounds__(256) void gemm_k(
    const float* __restrict__ A, size_t a_stride, size_t a_zoff,
    const float* __restrict__ B, int b_stride, int b_zoff,
    const float* __restrict__ bias, int bias_zoff,
    float* __restrict__ C, int c_stride, int c_zoff,
    int Kdim)
{
    __shared__ __align__(16) float As[2][16 * 68];   // padded rows: no bank conflict
    __shared__ __align__(16) float Bs[2][64 * 64];
    int tid = threadIdx.x;
    int tx = tid & 15, ty = tid >> 4;
    int t0 = blockIdx.x * 16;
    int n0 = blockIdx.y * 64;
    int z  = blockIdx.z;

    const float* Ab    = A + (size_t)z * a_zoff;
    const float* Bb    = B + (size_t)z * b_zoff + n0;
    const float* biasb = bias + (size_t)z * bias_zoff + n0;
    float*       Cb    = C + (size_t)z * c_zoff + n0;

    // per-thread staging coords: A 16x64 (1 float4/thread), B 64x64 (4 float4)
    int ar = ty, ac = tx * 4;
    const float* Aptr = Ab + (size_t)(t0 + ar) * a_stride + ac;
    const float* Bptr = Bb + (size_t)ty * b_stride + tx * 4;

    float4 pa, pb0, pb1, pb2, pb3;
    // prologue: load + store chunk 0
    pa  = *(const float4*)(Aptr);
    pb0 = *(const float4*)(Bptr);
    pb1 = *(const float4*)(Bptr + (size_t)16 * b_stride);
    pb2 = *(const float4*)(Bptr + (size_t)32 * b_stride);
    pb3 = *(const float4*)(Bptr + (size_t)48 * b_stride);
    *(float4*)&As[0][ar * 68 + ac]        = pa;
    *(float4*)&Bs[0][(ty     ) * 64 + tx * 4] = pb0;
    *(float4*)&Bs[0][(ty + 16) * 64 + tx * 4] = pb1;
    *(float4*)&Bs[0][(ty + 32) * 64 + tx * 4] = pb2;
    *(float4*)&Bs[0][(ty + 48) * 64 + tx * 4] = pb3;
    __syncthreads();

    u64t acc0 = 0ull, acc1 = 0ull;
    int nch = Kdim >> 6;
    for (int c = 0; c < nch; c++) {
        int cur = c & 1;
        if (c + 1 < nch) {   // prefetch next chunk into registers
            const float* Ap = Aptr + (c + 1) * 64;
            const float* Bp = Bptr + (size_t)(c + 1) * 64 * b_stride;
            pa  = *(const float4*)(Ap);
            pb0 = *(const float4*)(Bp);
            pb1 = *(const float4*)(Bp + (size_t)16 * b_stride);
            pb2 = *(const float4*)(Bp + (size_t)32 * b_stride);
            pb3 = *(const float4*)(Bp + (size_t)48 * b_stride);
        }
        const float* Asr = &As[cur][ty * 68];
        #pragma unroll
        for (int kk = 0; kk < 64; kk++) {
            u64t ap = pack2(Asr[kk], Asr[kk]);
            ulonglong2 bv = *(const ulonglong2*)&Bs[cur][kk * 64 + tx * 4];
            fma2(acc0, ap, bv.x);
            fma2(acc1, ap, bv.y);
        }
        if (c + 1 < nch) {   // store into the other buffer (safe: last read 2 its ago)
            int nxt = cur ^ 1;
            *(float4*)&As[nxt][ar * 68 + ac]            = pa;
            *(float4*)&Bs[nxt][(ty     ) * 64 + tx * 4] = pb0;
            *(float4*)&Bs[nxt][(ty + 16) * 64 + tx * 4] = pb1;
            *(float4*)&Bs[nxt][(ty + 32) * 64 + tx * 4] = pb2;
            *(float4*)&Bs[nxt][(ty + 48) * 64 + tx * 4] = pb3;
        }
        __syncthreads();
    }
    float2 a0 = unpack2(acc0), a1 = unpack2(acc1);
    float4 bb = *(const float4*)&biasb[tx * 4];
    float4 o  = make_float4(a0.x + bb.x, a0.y + bb.y, a1.x + bb.z, a1.y + bb.w);
    *(float4*)&Cb[(size_t)(t0 + ty) * c_stride + tx * 4] = o;
}

// ---------------- K2: P[t,h,d] = 0.125 * sum_j Q[t,h*64+j] * Wk[d, h*64+j] --
__global__ __launch_bounds__(256) void pproj_k(const float* __restrict__ Wk)
{
    __shared__ float As[16 * 64];
    __shared__ float Bt[64 * 68];   // transposed Wk slice, padded
    int tid = threadIdx.x;
    int tx = tid & 15, ty = tid >> 4;
    int t0 = blockIdx.x * 16;
    int d0 = blockIdx.y * 64;
    int h  = blockIdx.z;

    #pragma unroll
    for (int it = 0; it < 4; it++) {
        int i = tid + it * 256;
        int r = i >> 6, j = i & 63;
        As[i] = g_Q[(size_t)(t0 + r) * DMODEL + h * HD + j];
    }
    #pragma unroll
    for (int it = 0; it < 16; it++) {
        int i = tid + it * 256;
        int dd = i >> 6, j = i & 63;
        Bt[j * 68 + dd] = Wk[(size_t)(d0 + dd) * DMODEL + h * HD + j];
    }
    __syncthreads();

    float4 acc = make_float4(0.f, 0.f, 0.f, 0.f);
    #pragma unroll
    for (int j = 0; j < 64; j++) {
        float a  = As[ty * 64 + j];
        float4 b = *reinterpret_cast<const float4*>(&Bt[j * 68 + tx * 4]);
        acc.x += a * b.x; acc.y += a * b.y;
        acc.z += a * b.z; acc.w += a * b.w;
    }
    const float s = 0.125f;
    float4 o = make_float4(acc.x * s, acc.y * s, acc.z * s, acc.w * s);
    *reinterpret_cast<float4*>(
        &g_P[((size_t)(t0 + ty) * NH + h) * DMODEL + d0 + tx * 4]) = o;
}

// ---------------- K3: per-tile attention: logits -> softmax -> Y ------------
__global__ __launch_bounds__(256) void attn_k(const float* __restrict__ x,
                                              const float* __restrict__ bk)
{
    __shared__ __align__(16) u64t  Psp[DMODEL * 4];  // 16 KB: [d][pair h/2]
    __shared__ __align__(16) float Es[NTOK * 8];     // 8 KB:  [n][h] exp values
    __shared__ float Ls[NTOK * 8];                   // 8 KB:  [n][h] logits
    __shared__ float red[16];
    int tid = threadIdx.x;
    int t = blockIdx.x;
    const float* xt = x + (size_t)t * NTOK * DMODEL;

    // stage P pre-packed as f32x2 head-pairs (coalesced on d)
    const float* Pt = g_P + (size_t)t * NH * DMODEL;
    #pragma unroll
    for (int it = 0; it < 8; it++) {
        int i = tid + it * 256;          // 2048 pairs
        int d = i & 511, p = i >> 9;
        float lo = Pt[(size_t)(2 * p)     * DMODEL + d];
        float hi = Pt[(size_t)(2 * p + 1) * DMODEL + d];
        Psp[d * 4 + p] = pack2(lo, hi);
    }
    // c[h] = 0.125 * q_h . bk_h   (warp per head)
    {
        int h = tid >> 5, j = tid & 31;
        const float* Qt  = g_Q + (size_t)t * DMODEL + h * HD;
        const float* bkh = bk + h * HD;
        float p = Qt[j] * bkh[j] + Qt[j + 32] * bkh[j + 32];
        #pragma unroll
        for (int o = 16; o > 0; o >>= 1) p += __shfl_down_sync(0xffffffffu, p, o);
        if (j == 0) red[h] = 0.125f * p;
    }
    __syncthreads();

    // ---- phase 1: logits, thread = token row, direct gmem row reads
    u64t la[4];
    #pragma unroll
    for (int p = 0; p < 4; p++) la[p] = pack2(red[2 * p], red[2 * p + 1]);

    const float4* xr = reinterpret_cast<const float4*>(xt + (size_t)tid * DMODEL);
    #pragma unroll 4
    for (int dv = 0; dv < 128; dv++) {
        float4 xv = xr[dv];
        const u64t* Pp = &Psp[dv * 16];
        u64t xd;
        xd = pack2(xv.x, xv.x);
        fma2(la[0], xd, Pp[0]);  fma2(la[1], xd, Pp[1]);
        fma2(la[2], xd, Pp[2]);  fma2(la[3], xd, Pp[3]);
        xd = pack2(xv.y, xv.y);
        fma2(la[0], xd, Pp[4]);  fma2(la[1], xd, Pp[5]);
        fma2(la[2], xd, Pp[6]);  fma2(la[3], xd, Pp[7]);
        xd = pack2(xv.z, xv.z);
        fma2(la[0], xd, Pp[8]);  fma2(la[1], xd, Pp[9]);
        fma2(la[2], xd, Pp[10]); fma2(la[3], xd, Pp[11]);
        xd = pack2(xv.w, xv.w);
        fma2(la[0], xd, Pp[12]); fma2(la[1], xd, Pp[13]);
        fma2(la[2], xd, Pp[14]); fma2(la[3], xd, Pp[15]);
    }
    float l[8];
    #pragma unroll
    for (int p = 0; p < 4; p++) {
        float2 f = unpack2(la[p]);
        l[2 * p] = f.x; l[2 * p + 1] = f.y;
    }
    int n = tid;
    #pragma unroll
    for (int h = 0; h < 8; h++) Ls[n * 8 + h] = l[h];
    __syncthreads();

    // ---- softmax
    int wid = tid >> 5, lane = tid & 31;
    {   // max per head (warp per head)
        float m = -1e30f;
        for (int i = lane; i < 256; i += 32) m = fmaxf(m, Ls[i * 8 + wid]);
        #pragma unroll
        for (int o = 16; o > 0; o >>= 1)
            m = fmaxf(m, __shfl_xor_sync(0xffffffffu, m, o));
        if (lane == 0) red[wid] = m;
    }
    __syncthreads();
    #pragma unroll
    for (int h = 0; h < 8; h++) Es[n * 8 + h] = __expf(l[h] - red[h]);
    __syncthreads();
    {   // sum per head -> 1/s
        float s = 0.f;
        for (int i = lane; i < 256; i += 32) s += Es[i * 8 + wid];
        #pragma unroll
        for (int o = 16; o > 0; o >>= 1) s += __shfl_xor_sync(0xffffffffu, s, o);
        if (lane == 0) red[8 + wid] = 1.0f / s;
    }
    __syncthreads();

    // ---- phase 2: Y[h,d] = (1/s) sum_n e[n,h] x[n,d]; thread owns 2 columns
    u64t acc[8];
    #pragma unroll
    for (int h = 0; h < 8; h++) acc[h] = 0ull;
    const float2* x2 = reinterpret_cast<const float2*>(xt) + tid;
    const float4* Ev = reinterpret_cast<const float4*>(Es);
    #pragma unroll 8
    for (int nn = 0; nn < NTOK; nn++) {
        float2 xv = x2[(size_t)nn * 256];            // coalesced, L2-hit
        u64t xp = pack2(xv.x, xv.y);
        float4 e0 = Ev[nn * 2], e1 = Ev[nn * 2 + 1]; // LDS.128 broadcast
        fma2(acc[0], pack2(e0.x, e0.x), xp);
        fma2(acc[1], pack2(e0.y, e0.y), xp);
        fma2(acc[2], pack2(e0.z, e0.z), xp);
        fma2(acc[3], pack2(e0.w, e0.w), xp);
        fma2(acc[4], pack2(e1.x, e1.x), xp);
        fma2(acc[5], pack2(e1.y, e1.y), xp);
        fma2(acc[6], pack2(e1.z, e1.z), xp);
        fma2(acc[7], pack2(e1.w, e1.w), xp);
    }
    #pragma unroll
    for (int h = 0; h < 8; h++) {
        float inv = red[8 + h];
        float2 a = unpack2(acc[h]);
        float2 o; o.x = a.x * inv; o.y = a.y * inv;
        reinterpret_cast<float2*>(g_Y + ((size_t)t * NH + h) * DMODEL)[tid] = o;
    }
}

// ---------------------------------------------------------------------------
extern "C" void kernel_launch(void* const* d_in, const int* in_sizes, int n_in,
                              void* d_out, int out_size)
{
    const float* x  = (const float*)d_in[0];
    const float* Wq = (const float*)d_in[1];
    const float* bq = (const float*)d_in[2];
    const float* Wk = (const float*)d_in[3];
    const float* bk = (const float*)d_in[4];
    const float* Wv = (const float*)d_in[5];
    const float* bv = (const float*)d_in[6];
    const float* Wo = (const float*)d_in[7];
    const float* bo = (const float*)d_in[8];
    float* out = (float*)d_out;
    (void)in_sizes; (void)n_in; (void)out_size;

    void *pQ, *pY, *pC;
    cudaGetSymbolAddress(&pQ, g_Q);
    cudaGetSymbolAddress(&pY, g_Y);
    cudaGetSymbolAddress(&pC, g_ctx);

    // K1: Q = X0 @ Wq + bq
    gemm_k<<<dim3(16, 8, 1), 256>>>(
        x, (size_t)(NTOK * DMODEL), 0,
        Wq, DMODEL, 0, bq, 0,
        (float*)pQ, DMODEL, 0, DMODEL);

    // K2: P[t,h,d] (pre-scaled by 1/8)
    pproj_k<<<dim3(16, 8, NH), 256>>>(Wk);

    // K3: per-tile attention -> g_Y
    attn_k<<<TT, 256>>>(x, bk);

    // K4: ctx_h = Y_h @ Wv[:,h] + bv_h
    gemm_k<<<dim3(16, 1, NH), 256>>>(
        (const float*)pY, (size_t)(NH * DMODEL), (size_t)DMODEL,
        Wv, DMODEL, HD, bv, HD,
        (float*)pC, DMODEL, HD, DMODEL);

    // K5: out = ctx @ Wo + bo
    gemm_k<<<dim3(16, 8, 1), 256>>>(
        (const float*)pC, (size_t)DMODEL, 0,
        Wo, DMODEL, 0, bo, 0,
        out, DMODEL, 0, DMODEL);
}